// round 2
// baseline (speedup 1.0000x reference)
#include <cuda_runtime.h>
#include <cuda_bf16.h>

// Problem dims (fixed by the dataset)
#define BB   4
#define TQ   256
#define TV   1024
#define DD   512
#define AA   128

// Scratch buffers (device globals: allocation-free)
__device__ float g_K[BB * TV * AA];      // 2 MB
__device__ float g_Q[BB * TQ * AA];      // 0.5 MB
__device__ float g_attn[BB * TQ * TV];   // 4 MB

// ---------------------------------------------------------------------------
// fast math helpers
// ---------------------------------------------------------------------------
__device__ __forceinline__ float fast_ex2(float x) {
    float y;
    asm("ex2.approx.f32 %0, %1;" : "=f"(y) : "f"(x));
    return y;
}
__device__ __forceinline__ float fast_rcp(float x) {
    float y;
    asm("rcp.approx.f32 %0, %1;" : "=f"(y) : "f"(x));
    return y;
}
// tanh(x) = 1 - 2/(exp(2x)+1), via ex2/rcp approx (abs err ~1e-7)
__device__ __forceinline__ float ftanh(float x) {
    float e = fast_ex2(x * 2.8853900817779268f);  // 2*log2(e)
    float r = fast_rcp(e + 1.0f);
    return fmaf(-2.0f, r, 1.0f);
}

// ---------------------------------------------------------------------------
// Kernel A: projection  out[M,128] = X[M,512] @ W[512,128] + b
// BM=32, BN=128, BK=16, 256 threads, micro-tile 4x4
// which: 0 -> g_K, 1 -> g_Q
// ---------------------------------------------------------------------------
__global__ void __launch_bounds__(256) proj_kernel(
    const float* __restrict__ X, const float* __restrict__ W,
    const float* __restrict__ bias, int which)
{
    __shared__ float Xs[32][16];
    __shared__ float Ws[16][128];

    float* out = which ? g_Q : g_K;

    const int t  = threadIdx.x;
    const int tx = t & 31;        // col group: cols tx*4 .. tx*4+3
    const int ty = t >> 5;        // row group: rows ty*4 .. ty*4+3
    const int r0 = blockIdx.x * 32;

    float acc[4][4] = {};

    for (int k0 = 0; k0 < DD; k0 += 16) {
        if (t < 128) {
            int row = t >> 2, c4 = (t & 3) * 4;
            *(float4*)&Xs[row][c4] =
                *(const float4*)&X[(size_t)(r0 + row) * DD + k0 + c4];
        }
#pragma unroll
        for (int i = 0; i < 2; ++i) {           // 16*128 floats = 512 float4
            int f = i * 256 + t;
            int rr = f >> 5, c4 = (f & 31) * 4;
            *(float4*)&Ws[rr][c4] =
                *(const float4*)&W[(size_t)(k0 + rr) * AA + c4];
        }
        __syncthreads();
#pragma unroll
        for (int k = 0; k < 16; ++k) {
            float4 wv = *(const float4*)&Ws[k][tx * 4];
#pragma unroll
            for (int r = 0; r < 4; ++r) {
                float xv = Xs[ty * 4 + r][k];
                acc[r][0] = fmaf(xv, wv.x, acc[r][0]);
                acc[r][1] = fmaf(xv, wv.y, acc[r][1]);
                acc[r][2] = fmaf(xv, wv.z, acc[r][2]);
                acc[r][3] = fmaf(xv, wv.w, acc[r][3]);
            }
        }
        __syncthreads();
    }

    float b0 = bias[tx * 4 + 0], b1 = bias[tx * 4 + 1];
    float b2 = bias[tx * 4 + 2], b3 = bias[tx * 4 + 3];
#pragma unroll
    for (int r = 0; r < 4; ++r) {
        float4 o;
        o.x = acc[r][0] + b0; o.y = acc[r][1] + b1;
        o.z = acc[r][2] + b2; o.w = acc[r][3] + b3;
        *(float4*)&out[(size_t)(r0 + ty * 4 + r) * AA + tx * 4] = o;
    }
}

// ---------------------------------------------------------------------------
// Kernel B: scores + softmax.
// grid: (TQ/4, B), 256 threads.
// Per CTA: 4 q-rows. v tiled in 8 tiles of 128 (K tile transposed in smem).
// score[q,v] = sum_a attn_v[a] * tanh(Q[q,a] + K[v,a]), then masked softmax.
// Dynamic smem layout (floats):
//   KsT[128][130]  (a-major, 2-way-conflict transpose store, float2 loads)
//   Qs[4*128], av[128], sc[4*1024]
// ---------------------------------------------------------------------------
#define KST_STRIDE 130
#define SMEMB_FLOATS (128 * KST_STRIDE + 4 * 128 + 128 + 4 * 1024)

__global__ void __launch_bounds__(256, 2) score_softmax_kernel(
    const int* __restrict__ mask, const float* __restrict__ attn_v)
{
    extern __shared__ float sm[];
    float* KsT = sm;                         // 128*130
    float* Qs  = KsT + 128 * KST_STRIDE;     // 512
    float* av  = Qs + 4 * 128;               // 128
    float* sc  = av + 128;                   // 4096

    const int t  = threadIdx.x;
    const int b  = blockIdx.y;
    const int q0 = blockIdx.x * 4;

    // load Q rows + attn_v
    if (t < 128) {
        *(float4*)&Qs[t * 4] =
            *(const float4*)&g_Q[((size_t)(b * TQ + q0)) * AA + t * 4];
        av[t] = attn_v[t];
    }

    const int v0 = (t & 63) * 2;   // 2 adjacent v per thread
    const int q  = t >> 6;         // 0..3
    const int al = t & 127;        // a for the fill loop
    const int vh = t >> 7;         // 0/1

    for (int vt = 0; vt < TV / 128; ++vt) {
        const int vbase = vt * 128;
        __syncthreads();   // protect KsT (and first-iter Qs/av) before refill
        // fill KsT[a][v] from g_K[b][vbase+v][a] (transposed)
        const float* Kp = g_K + ((size_t)b * TV + vbase) * AA;
#pragma unroll 8
        for (int i = 0; i < 64; ++i) {
            int vl = vh + 2 * i;
            KsT[al * KST_STRIDE + vl] = Kp[(size_t)vl * AA + al];
        }
        __syncthreads();

        float a0 = 0.f, a1 = 0.f;
#pragma unroll 4
        for (int a = 0; a < AA; ++a) {
            float2 kv = *(const float2*)&KsT[a * KST_STRIDE + v0];
            float qv = Qs[q * AA + a];
            float va = av[a];
            a0 = fmaf(va, ftanh(qv + kv.x), a0);
            a1 = fmaf(va, ftanh(qv + kv.y), a1);
        }
        *(float2*)&sc[q * TV + vbase + v0] = make_float2(a0, a1);
    }
    __syncthreads();

    // softmax: warp w (<4) handles row w
    const int w = t >> 5, lane = t & 31;
    if (w < 4) {
        float* row = sc + w * TV;
        const int* mrow = mask + (size_t)b * TV;
        float mx = -3.4e38f;
        for (int j = lane; j < TV; j += 32) {
            float s = row[j] + (1.0f - (float)mrow[j]) * (-1e9f);
            row[j] = s;
            mx = fmaxf(mx, s);
        }
#pragma unroll
        for (int o = 16; o; o >>= 1) mx = fmaxf(mx, __shfl_xor_sync(~0u, mx, o));
        float sum = 0.f;
        for (int j = lane; j < TV; j += 32) {
            float e = fast_ex2((row[j] - mx) * 1.4426950408889634f);
            row[j] = e;
            sum += e;
        }
#pragma unroll
        for (int o = 16; o; o >>= 1) sum += __shfl_xor_sync(~0u, sum, o);
        float inv = 1.0f / sum;
        float* arow = g_attn + ((size_t)(b * TQ + q0 + w)) * TV;
        for (int j = lane; j < TV; j += 32) arow[j] = row[j] * inv;
    }
}

// ---------------------------------------------------------------------------
// Kernel C: out[b,q,d] = sum_v attn[b,q,v] * inputs[b,v,d]
// BM=32(q), BN=128(d), BK=32(v), 256 threads, micro 4x4.
// grid: (DD/128=4, TQ/32=8, B=4) = 128 CTAs
// ---------------------------------------------------------------------------
__global__ void __launch_bounds__(256) av_kernel(
    const float* __restrict__ inp, float* __restrict__ out)
{
    __shared__ float As[32][33];
    __shared__ float Is[32][128];

    const int t  = threadIdx.x;
    const int tx = t & 31;
    const int ty = t >> 5;
    const int b  = blockIdx.z;
    const int q0 = blockIdx.y * 32;
    const int d0 = blockIdx.x * 128;

    float acc[4][4] = {};

    for (int v0 = 0; v0 < TV; v0 += 32) {
#pragma unroll
        for (int i = 0; i < 4; ++i) {
            int r = ty + i * 8;
            As[r][tx] = g_attn[((size_t)(b * TQ + q0 + r)) * TV + v0 + tx];
        }
        // Is is 32x128 floats = 1024 float4 -> need 4 passes of 256 threads
#pragma unroll
        for (int i = 0; i < 4; ++i) {
            int f = i * 256 + t;
            int r = f >> 5, c4 = (f & 31) * 4;
            *(float4*)&Is[r][c4] =
                *(const float4*)&inp[((size_t)(b * TV + v0 + r)) * DD + d0 + c4];
        }
        __syncthreads();
#pragma unroll
        for (int k = 0; k < 32; ++k) {
            float4 iv = *(const float4*)&Is[k][tx * 4];
#pragma unroll
            for (int r = 0; r < 4; ++r) {
                float a = As[ty * 4 + r][k];
                acc[r][0] = fmaf(a, iv.x, acc[r][0]);
                acc[r][1] = fmaf(a, iv.y, acc[r][1]);
                acc[r][2] = fmaf(a, iv.z, acc[r][2]);
                acc[r][3] = fmaf(a, iv.w, acc[r][3]);
            }
        }
        __syncthreads();
    }

#pragma unroll
    for (int r = 0; r < 4; ++r) {
        float4 o;
        o.x = acc[r][0]; o.y = acc[r][1]; o.z = acc[r][2]; o.w = acc[r][3];
        *(float4*)&out[((size_t)(b * TQ + q0 + ty * 4 + r)) * DD + d0 + tx * 4] = o;
    }
}

// ---------------------------------------------------------------------------
extern "C" void kernel_launch(void* const* d_in, const int* in_sizes, int n_in,
                              void* d_out, int out_size)
{
    (void)in_sizes; (void)n_in; (void)out_size;
    const float* inputs  = (const float*)d_in[0];   // [B,Tv,D]
    const float* context = (const float*)d_in[1];   // [B,Tq,D]
    const int*   mask    = (const int*)  d_in[2];   // [B,Tv]
    const float* Wk      = (const float*)d_in[3];   // [D,A]
    const float* bk      = (const float*)d_in[4];   // [A]
    const float* Wq      = (const float*)d_in[5];   // [D,A]
    const float* bq      = (const float*)d_in[6];   // [A]
    const float* attn_v  = (const float*)d_in[7];   // [A]
    float* out = (float*)d_out;                     // [B,Tq,D]

    static const size_t smemB = SMEMB_FLOATS * sizeof(float);
    cudaFuncSetAttribute(score_softmax_kernel,
                         cudaFuncAttributeMaxDynamicSharedMemorySize, (int)smemB);

    // K = inputs @ Wk + bk   (M = B*Tv = 4096)
    proj_kernel<<<(BB * TV) / 32, 256>>>(inputs, Wk, bk, /*which=*/0);
    // Q = context @ Wq + bq  (M = B*Tq = 1024)
    proj_kernel<<<(BB * TQ) / 32, 256>>>(context, Wq, bq, /*which=*/1);
    // scores + softmax -> g_attn
    {
        dim3 grid(TQ / 4, BB);
        score_softmax_kernel<<<grid, 256, smemB>>>(mask, attn_v);
    }
    // out = attn @ inputs
    {
        dim3 grid(DD / 128, TQ / 32, BB);
        av_kernel<<<grid, 256>>>(inputs, out);
    }
}

// round 4
// speedup vs baseline: 1.2464x; 1.2464x over previous
#include <cuda_runtime.h>
#include <cuda_bf16.h>

// Problem dims (fixed by the dataset)
#define BB   4
#define TQ   256
#define TV   1024
#define DD   512
#define AA   128

// Scratch buffers (device globals: allocation-free)
__device__ float g_K[BB * TV * AA];      // 2 MB
__device__ float g_Q[BB * TQ * AA];      // 0.5 MB
__device__ float g_attn[BB * TQ * TV];   // 4 MB

// ---------------------------------------------------------------------------
// fast math helpers
// ---------------------------------------------------------------------------
__device__ __forceinline__ float fast_ex2(float x) {
    float y;
    asm("ex2.approx.f32 %0, %1;" : "=f"(y) : "f"(x));
    return y;
}
// single-MUFU tanh (sm_75+); abs err ~5e-4 per element, fine through the
// 128-term weighted sum + softmax (target rel_err 1e-3)
__device__ __forceinline__ float ftanh(float x) {
    float y;
    asm("tanh.approx.f32 %0, %1;" : "=f"(y) : "f"(x));
    return y;
}

// ---------------------------------------------------------------------------
// Kernel A: fused K/Q projection.
// out[M,128] = X[M,512] @ W[512,128] + b
// BM=16, BN=128, BK=16, 256 threads, micro 2x4.
// grid = BB*TV/16 + BB*TQ/16 = 256 + 64 = 320 CTAs.
// ---------------------------------------------------------------------------
#define PROJ_KBLKS ((BB * TV) / 16)   // 256

__global__ void __launch_bounds__(256) proj_kernel(
    const float* __restrict__ inputs, const float* __restrict__ context,
    const float* __restrict__ Wk, const float* __restrict__ bk,
    const float* __restrict__ Wq, const float* __restrict__ bq)
{
    __shared__ float Xs[16][16];   // stride 16: float4-aligned; compute reads
                                   // are warp-broadcast, so no padding needed
    __shared__ float Ws[16][128];

    const int bx = blockIdx.x;
    const bool isK = (bx < PROJ_KBLKS);
    const float* X    = isK ? inputs : context;
    const float* W    = isK ? Wk : Wq;
    const float* bias = isK ? bk : bq;
    float* out        = isK ? g_K : g_Q;
    const int r0 = (isK ? bx : (bx - PROJ_KBLKS)) * 16;

    const int t  = threadIdx.x;
    const int tx = t & 31;        // col group: cols tx*4 .. tx*4+3
    const int ty = t >> 5;        // row group: rows ty*2, ty*2+1

    float acc[2][4] = {};

    for (int k0 = 0; k0 < DD; k0 += 16) {
        if (t < 64) {             // 16x16 floats = 64 float4
            int row = t >> 2, c4 = (t & 3) * 4;
            *(float4*)&Xs[row][c4] =
                *(const float4*)&X[(size_t)(r0 + row) * DD + k0 + c4];
        }
#pragma unroll
        for (int i = 0; i < 2; ++i) {           // 16*128 floats = 512 float4
            int f = i * 256 + t;
            int rr = f >> 5, c4 = (f & 31) * 4;
            *(float4*)&Ws[rr][c4] =
                *(const float4*)&W[(size_t)(k0 + rr) * AA + c4];
        }
        __syncthreads();
#pragma unroll
        for (int k = 0; k < 16; ++k) {
            float4 wv = *(const float4*)&Ws[k][tx * 4];
#pragma unroll
            for (int r = 0; r < 2; ++r) {
                float xv = Xs[ty * 2 + r][k];
                acc[r][0] = fmaf(xv, wv.x, acc[r][0]);
                acc[r][1] = fmaf(xv, wv.y, acc[r][1]);
                acc[r][2] = fmaf(xv, wv.z, acc[r][2]);
                acc[r][3] = fmaf(xv, wv.w, acc[r][3]);
            }
        }
        __syncthreads();
    }

    float b0 = bias[tx * 4 + 0], b1 = bias[tx * 4 + 1];
    float b2 = bias[tx * 4 + 2], b3 = bias[tx * 4 + 3];
#pragma unroll
    for (int r = 0; r < 2; ++r) {
        float4 o;
        o.x = acc[r][0] + b0; o.y = acc[r][1] + b1;
        o.z = acc[r][2] + b2; o.w = acc[r][3] + b3;
        *(float4*)&out[(size_t)(r0 + ty * 2 + r) * AA + tx * 4] = o;
    }
}

// ---------------------------------------------------------------------------
// Kernel B: scores + softmax.
// grid: (TQ/4, B), 256 threads.
// Per CTA: 4 q-rows. v tiled in 8 tiles of 128 (K tile transposed in smem).
// score[q,v] = sum_a attn_v[a] * tanh(Q[q,a] + K[v,a]), then masked softmax.
// ---------------------------------------------------------------------------
#define KST_STRIDE 130
#define SMEMB_FLOATS (128 * KST_STRIDE + 4 * 128 + 128 + 4 * 1024)

__global__ void __launch_bounds__(256, 2) score_softmax_kernel(
    const int* __restrict__ mask, const float* __restrict__ attn_v)
{
    extern __shared__ float sm[];
    float* KsT = sm;                         // 128*130
    float* Qs  = KsT + 128 * KST_STRIDE;     // 512
    float* av  = Qs + 4 * 128;               // 128
    float* sc  = av + 128;                   // 4096

    const int t  = threadIdx.x;
    const int b  = blockIdx.y;
    const int q0 = blockIdx.x * 4;

    // load Q rows + attn_v
    if (t < 128) {
        *(float4*)&Qs[t * 4] =
            *(const float4*)&g_Q[((size_t)(b * TQ + q0)) * AA + t * 4];
        av[t] = attn_v[t];
    }

    const int v0 = (t & 63) * 2;   // 2 adjacent v per thread
    const int q  = t >> 6;         // 0..3
    const int al = t & 127;        // a for the fill loop
    const int vh = t >> 7;         // 0/1

    for (int vt = 0; vt < TV / 128; ++vt) {
        const int vbase = vt * 128;
        __syncthreads();   // protect KsT (and first-iter Qs/av) before refill
        // fill KsT[a][v] from g_K[b][vbase+v][a] (transposed)
        const float* Kp = g_K + ((size_t)b * TV + vbase) * AA;
#pragma unroll 8
        for (int i = 0; i < 64; ++i) {
            int vl = vh + 2 * i;
            KsT[al * KST_STRIDE + vl] = Kp[(size_t)vl * AA + al];
        }
        __syncthreads();

        float a0 = 0.f, a1 = 0.f;
#pragma unroll 4
        for (int a = 0; a < AA; ++a) {
            float2 kv = *(const float2*)&KsT[a * KST_STRIDE + v0];
            float qv = Qs[q * AA + a];
            float va = av[a];
            a0 = fmaf(va, ftanh(qv + kv.x), a0);
            a1 = fmaf(va, ftanh(qv + kv.y), a1);
        }
        *(float2*)&sc[q * TV + vbase + v0] = make_float2(a0, a1);
    }
    __syncthreads();

    // softmax: warp w (<4) handles row w
    const int w = t >> 5, lane = t & 31;
    if (w < 4) {
        float* row = sc + w * TV;
        const int* mrow = mask + (size_t)b * TV;
        float mx = -3.4e38f;
        for (int j = lane; j < TV; j += 32) {
            float s = row[j] + (1.0f - (float)mrow[j]) * (-1e9f);
            row[j] = s;
            mx = fmaxf(mx, s);
        }
#pragma unroll
        for (int o = 16; o; o >>= 1) mx = fmaxf(mx, __shfl_xor_sync(~0u, mx, o));
        float sum = 0.f;
        for (int j = lane; j < TV; j += 32) {
            float e = fast_ex2((row[j] - mx) * 1.4426950408889634f);
            row[j] = e;
            sum += e;
        }
#pragma unroll
        for (int o = 16; o; o >>= 1) sum += __shfl_xor_sync(~0u, sum, o);
        float inv = 1.0f / sum;
        float* arow = g_attn + ((size_t)(b * TQ + q0 + w)) * TV;
        for (int j = lane; j < TV; j += 32) arow[j] = row[j] * inv;
    }
}

// ---------------------------------------------------------------------------
// Kernel C: out[b,q,d] = sum_v attn[b,q,v] * inputs[b,v,d]
// BM=32(q), BN=64(d), BK=32(v), 256 threads, micro 2x4.
// grid: (DD/64=8, TQ/32=8, B=4) = 256 CTAs -> 2 co-resident per SM.
// ---------------------------------------------------------------------------
__global__ void __launch_bounds__(256) av_kernel(
    const float* __restrict__ inp, float* __restrict__ out)
{
    __shared__ float As[32][33];
    __shared__ float Is[32][64];

    const int t  = threadIdx.x;
    const int tx = t & 15;        // col group: cols tx*4 .. tx*4+3 (of 64)
    const int ty = t >> 4;        // row group: rows ty*2, ty*2+1 (of 32)
    const int b  = blockIdx.z;
    const int q0 = blockIdx.y * 32;
    const int d0 = blockIdx.x * 64;

    float acc[2][4] = {};

    for (int v0 = 0; v0 < TV; v0 += 32) {
        // As: 32x32 floats = 1024, 4 per thread
#pragma unroll
        for (int i = 0; i < 4; ++i) {
            int f = i * 256 + t;
            int r = f >> 5, c = f & 31;
            As[r][c] = g_attn[((size_t)(b * TQ + q0 + r)) * TV + v0 + c];
        }
        // Is: 32x64 floats = 512 float4, 2 per thread
#pragma unroll
        for (int i = 0; i < 2; ++i) {
            int f = i * 256 + t;
            int r = f >> 4, c4 = (f & 15) * 4;
            *(float4*)&Is[r][c4] =
                *(const float4*)&inp[((size_t)(b * TV + v0 + r)) * DD + d0 + c4];
        }
        __syncthreads();
#pragma unroll
        for (int k = 0; k < 32; ++k) {
            float4 iv = *(const float4*)&Is[k][tx * 4];
#pragma unroll
            for (int r = 0; r < 2; ++r) {
                float a = As[ty * 2 + r][k];
                acc[r][0] = fmaf(a, iv.x, acc[r][0]);
                acc[r][1] = fmaf(a, iv.y, acc[r][1]);
                acc[r][2] = fmaf(a, iv.z, acc[r][2]);
                acc[r][3] = fmaf(a, iv.w, acc[r][3]);
            }
        }
        __syncthreads();
    }

#pragma unroll
    for (int r = 0; r < 2; ++r) {
        float4 o;
        o.x = acc[r][0]; o.y = acc[r][1]; o.z = acc[r][2]; o.w = acc[r][3];
        *(float4*)&out[((size_t)(b * TQ + q0 + ty * 2 + r)) * DD + d0 + tx * 4] = o;
    }
}

// ---------------------------------------------------------------------------
extern "C" void kernel_launch(void* const* d_in, const int* in_sizes, int n_in,
                              void* d_out, int out_size)
{
    (void)in_sizes; (void)n_in; (void)out_size;
    const float* inputs  = (const float*)d_in[0];   // [B,Tv,D]
    const float* context = (const float*)d_in[1];   // [B,Tq,D]
    const int*   mask    = (const int*)  d_in[2];   // [B,Tv]
    const float* Wk      = (const float*)d_in[3];   // [D,A]
    const float* bk      = (const float*)d_in[4];   // [A]
    const float* Wq      = (const float*)d_in[5];   // [D,A]
    const float* bq      = (const float*)d_in[6];   // [A]
    const float* attn_v  = (const float*)d_in[7];   // [A]
    float* out = (float*)d_out;                     // [B,Tq,D]

    static const size_t smemB = SMEMB_FLOATS * sizeof(float);
    cudaFuncSetAttribute(score_softmax_kernel,
                         cudaFuncAttributeMaxDynamicSharedMemorySize, (int)smemB);

    // K = inputs @ Wk + bk ; Q = context @ Wq + bq  (fused, 320 CTAs)
    proj_kernel<<<PROJ_KBLKS + (BB * TQ) / 16, 256>>>(
        inputs, context, Wk, bk, Wq, bq);
    // scores + softmax -> g_attn
    {
        dim3 grid(TQ / 4, BB);
        score_softmax_kernel<<<grid, 256, smemB>>>(mask, attn_v);
    }
    // out = attn @ inputs
    {
        dim3 grid(DD / 64, TQ / 32, BB);
        av_kernel<<<grid, 256>>>(inputs, out);
    }
}

// round 5
// speedup vs baseline: 1.2573x; 1.0087x over previous
#include <cuda_runtime.h>
#include <cuda_bf16.h>

// Problem dims (fixed by the dataset)
#define BB   4
#define TQ   256
#define TV   1024
#define DD   512
#define AA   128

// Scratch buffers (device globals: allocation-free)
__device__ float g_K[BB * TV * AA];      // 2 MB
__device__ float g_Q[BB * TQ * AA];      // 0.5 MB
__device__ float g_attn[BB * TQ * TV];   // 4 MB

// ---------------------------------------------------------------------------
// fast math helpers
// ---------------------------------------------------------------------------
__device__ __forceinline__ float fast_ex2(float x) {
    float y;
    asm("ex2.approx.f32 %0, %1;" : "=f"(y) : "f"(x));
    return y;
}
// single-MUFU tanh (sm_75+); abs err ~5e-4 per element, measured harmless
// (rel_err 2.4e-6 end-to-end) through the weighted sum + softmax
__device__ __forceinline__ float ftanh(float x) {
    float y;
    asm("tanh.approx.f32 %0, %1;" : "=f"(y) : "f"(x));
    return y;
}

// ---------------------------------------------------------------------------
// Kernel A: fused K/Q projection.
// out[M,128] = X[M,512] @ W[512,128] + b
// BM=32, BN=128, BK=32, 256 threads, micro 4x4 (16 acc/thread).
// grid = BB*TV/32 + BB*TQ/32 = 128 + 32 = 160 CTAs.
// ---------------------------------------------------------------------------
#define PROJ_KBLKS ((BB * TV) / 32)   // 128

__global__ void __launch_bounds__(256) proj_kernel(
    const float* __restrict__ inputs, const float* __restrict__ context,
    const float* __restrict__ Wk, const float* __restrict__ bk,
    const float* __restrict__ Wq, const float* __restrict__ bq)
{
    __shared__ float Xs[32][32];   // compute reads are warp-broadcast
    __shared__ float Ws[32][128];

    const int bx = blockIdx.x;
    const bool isK = (bx < PROJ_KBLKS);
    const float* X    = isK ? inputs : context;
    const float* W    = isK ? Wk : Wq;
    const float* bias = isK ? bk : bq;
    float* out        = isK ? g_K : g_Q;
    const int r0 = (isK ? bx : (bx - PROJ_KBLKS)) * 32;

    const int t  = threadIdx.x;
    const int tx = t & 31;        // col group: cols tx*4 .. tx*4+3
    const int ty = t >> 5;        // row group: rows ty*4 .. ty*4+3

    float acc[4][4] = {};

    for (int k0 = 0; k0 < DD; k0 += 32) {
        // Xs: 32x32 floats = 256 float4, 1 per thread
        {
            int row = t >> 3, c4 = (t & 7) * 4;
            *(float4*)&Xs[row][c4] =
                *(const float4*)&X[(size_t)(r0 + row) * DD + k0 + c4];
        }
        // Ws: 32x128 floats = 1024 float4, 4 per thread
#pragma unroll
        for (int i = 0; i < 4; ++i) {
            int f = i * 256 + t;
            int rr = f >> 5, c4 = (f & 31) * 4;
            *(float4*)&Ws[rr][c4] =
                *(const float4*)&W[(size_t)(k0 + rr) * AA + c4];
        }
        __syncthreads();
#pragma unroll
        for (int k = 0; k < 32; ++k) {
            float4 wv = *(const float4*)&Ws[k][tx * 4];
#pragma unroll
            for (int r = 0; r < 4; ++r) {
                float xv = Xs[ty * 4 + r][k];
                acc[r][0] = fmaf(xv, wv.x, acc[r][0]);
                acc[r][1] = fmaf(xv, wv.y, acc[r][1]);
                acc[r][2] = fmaf(xv, wv.z, acc[r][2]);
                acc[r][3] = fmaf(xv, wv.w, acc[r][3]);
            }
        }
        __syncthreads();
    }

    float b0 = bias[tx * 4 + 0], b1 = bias[tx * 4 + 1];
    float b2 = bias[tx * 4 + 2], b3 = bias[tx * 4 + 3];
#pragma unroll
    for (int r = 0; r < 4; ++r) {
        float4 o;
        o.x = acc[r][0] + b0; o.y = acc[r][1] + b1;
        o.z = acc[r][2] + b2; o.w = acc[r][3] + b3;
        *(float4*)&out[(size_t)(r0 + ty * 4 + r) * AA + tx * 4] = o;
    }
}

// ---------------------------------------------------------------------------
// Kernel B: scores + softmax.
// grid: (TQ/4, B), 256 threads.
// Per CTA: 4 q-rows. v tiled in 8 tiles of 128 (K tile transposed in smem).
// score[q,v] = sum_a attn_v[a] * tanh(Q[q,a] + K[v,a]), then masked softmax.
// ---------------------------------------------------------------------------
#define KST_STRIDE 130
#define SMEMB_FLOATS (128 * KST_STRIDE + 4 * 128 + 128 + 4 * 1024)

__global__ void __launch_bounds__(256, 2) score_softmax_kernel(
    const int* __restrict__ mask, const float* __restrict__ attn_v)
{
    extern __shared__ float sm[];
    float* KsT = sm;                         // 128*130
    float* Qs  = KsT + 128 * KST_STRIDE;     // 512
    float* av  = Qs + 4 * 128;               // 128
    float* sc  = av + 128;                   // 4096

    const int t  = threadIdx.x;
    const int b  = blockIdx.y;
    const int q0 = blockIdx.x * 4;

    // load Q rows + attn_v
    if (t < 128) {
        *(float4*)&Qs[t * 4] =
            *(const float4*)&g_Q[((size_t)(b * TQ + q0)) * AA + t * 4];
        av[t] = attn_v[t];
    }

    const int v0 = (t & 63) * 2;   // 2 adjacent v per thread
    const int q  = t >> 6;         // 0..3
    const int al = t & 127;        // a for the fill loop
    const int vh = t >> 7;         // 0/1

    for (int vt = 0; vt < TV / 128; ++vt) {
        const int vbase = vt * 128;
        __syncthreads();   // protect KsT (and first-iter Qs/av) before refill
        // fill KsT[a][v] from g_K[b][vbase+v][a] (transposed)
        const float* Kp = g_K + ((size_t)b * TV + vbase) * AA;
#pragma unroll 8
        for (int i = 0; i < 64; ++i) {
            int vl = vh + 2 * i;
            KsT[al * KST_STRIDE + vl] = Kp[(size_t)vl * AA + al];
        }
        __syncthreads();

        float a0 = 0.f, a1 = 0.f;
#pragma unroll 4
        for (int a = 0; a < AA; ++a) {
            float2 kv = *(const float2*)&KsT[a * KST_STRIDE + v0];
            float qv = Qs[q * AA + a];
            float va = av[a];
            a0 = fmaf(va, ftanh(qv + kv.x), a0);
            a1 = fmaf(va, ftanh(qv + kv.y), a1);
        }
        *(float2*)&sc[q * TV + vbase + v0] = make_float2(a0, a1);
    }
    __syncthreads();

    // softmax: warp w (<4) handles row w
    const int w = t >> 5, lane = t & 31;
    if (w < 4) {
        float* row = sc + w * TV;
        const int* mrow = mask + (size_t)b * TV;
        float mx = -3.4e38f;
        for (int j = lane; j < TV; j += 32) {
            float s = row[j] + (1.0f - (float)mrow[j]) * (-1e9f);
            row[j] = s;
            mx = fmaxf(mx, s);
        }
#pragma unroll
        for (int o = 16; o; o >>= 1) mx = fmaxf(mx, __shfl_xor_sync(~0u, mx, o));
        float sum = 0.f;
        for (int j = lane; j < TV; j += 32) {
            float e = fast_ex2((row[j] - mx) * 1.4426950408889634f);
            row[j] = e;
            sum += e;
        }
#pragma unroll
        for (int o = 16; o; o >>= 1) sum += __shfl_xor_sync(~0u, sum, o);
        float inv = 1.0f / sum;
        float* arow = g_attn + ((size_t)(b * TQ + q0 + w)) * TV;
        for (int j = lane; j < TV; j += 32) arow[j] = row[j] * inv;
    }
}

// ---------------------------------------------------------------------------
// Kernel C: out[b,q,d] = sum_v attn[b,q,v] * inputs[b,v,d]
// BM=32(q), BN=64(d), BK=32(v), 256 threads, micro 2x4.
// grid: (DD/64=8, TQ/32=8, B=4) = 256 CTAs -> 2 co-resident per SM.
// ---------------------------------------------------------------------------
__global__ void __launch_bounds__(256) av_kernel(
    const float* __restrict__ inp, float* __restrict__ out)
{
    __shared__ float As[32][33];
    __shared__ float Is[32][64];

    const int t  = threadIdx.x;
    const int tx = t & 15;        // col group: cols tx*4 .. tx*4+3 (of 64)
    const int ty = t >> 4;        // row group: rows ty*2, ty*2+1 (of 32)
    const int b  = blockIdx.z;
    const int q0 = blockIdx.y * 32;
    const int d0 = blockIdx.x * 64;

    float acc[2][4] = {};

    for (int v0 = 0; v0 < TV; v0 += 32) {
        // As: 32x32 floats = 1024, 4 per thread
#pragma unroll
        for (int i = 0; i < 4; ++i) {
            int f = i * 256 + t;
            int r = f >> 5, c = f & 31;
            As[r][c] = g_attn[((size_t)(b * TQ + q0 + r)) * TV + v0 + c];
        }
        // Is: 32x64 floats = 512 float4, 2 per thread
#pragma unroll
        for (int i = 0; i < 2; ++i) {
            int f = i * 256 + t;
            int r = f >> 4, c4 = (f & 15) * 4;
            *(float4*)&Is[r][c4] =
                *(const float4*)&inp[((size_t)(b * TV + v0 + r)) * DD + d0 + c4];
        }
        __syncthreads();
#pragma unroll
        for (int k = 0; k < 32; ++k) {
            float4 iv = *(const float4*)&Is[k][tx * 4];
#pragma unroll
            for (int r = 0; r < 2; ++r) {
                float a = As[ty * 2 + r][k];
                acc[r][0] = fmaf(a, iv.x, acc[r][0]);
                acc[r][1] = fmaf(a, iv.y, acc[r][1]);
                acc[r][2] = fmaf(a, iv.z, acc[r][2]);
                acc[r][3] = fmaf(a, iv.w, acc[r][3]);
            }
        }
        __syncthreads();
    }

#pragma unroll
    for (int r = 0; r < 2; ++r) {
        float4 o;
        o.x = acc[r][0]; o.y = acc[r][1]; o.z = acc[r][2]; o.w = acc[r][3];
        *(float4*)&out[((size_t)(b * TQ + q0 + ty * 2 + r)) * DD + d0 + tx * 4] = o;
    }
}

// ---------------------------------------------------------------------------
extern "C" void kernel_launch(void* const* d_in, const int* in_sizes, int n_in,
                              void* d_out, int out_size)
{
    (void)in_sizes; (void)n_in; (void)out_size;
    const float* inputs  = (const float*)d_in[0];   // [B,Tv,D]
    const float* context = (const float*)d_in[1];   // [B,Tq,D]
    const int*   mask    = (const int*)  d_in[2];   // [B,Tv]
    const float* Wk      = (const float*)d_in[3];   // [D,A]
    const float* bk      = (const float*)d_in[4];   // [A]
    const float* Wq      = (const float*)d_in[5];   // [D,A]
    const float* bq      = (const float*)d_in[6];   // [A]
    const float* attn_v  = (const float*)d_in[7];   // [A]
    float* out = (float*)d_out;                     // [B,Tq,D]

    static const size_t smemB = SMEMB_FLOATS * sizeof(float);
    cudaFuncSetAttribute(score_softmax_kernel,
                         cudaFuncAttributeMaxDynamicSharedMemorySize, (int)smemB);

    // K = inputs @ Wk + bk ; Q = context @ Wq + bq  (fused, 160 CTAs)
    proj_kernel<<<PROJ_KBLKS + (BB * TQ) / 32, 256>>>(
        inputs, context, Wk, bk, Wq, bq);
    // scores + softmax -> g_attn
    {
        dim3 grid(TQ / 4, BB);
        score_softmax_kernel<<<grid, 256, smemB>>>(mask, attn_v);
    }
    // out = attn @ inputs
    {
        dim3 grid(DD / 64, TQ / 32, BB);
        av_kernel<<<grid, 256>>>(inputs, out);
    }
}

// round 7
// speedup vs baseline: 1.3468x; 1.0712x over previous
#include <cuda_runtime.h>
#include <cuda_bf16.h>

// Problem dims (fixed by the dataset)
#define BB   4
#define TQ   256
#define TV   1024
#define DD   512
#define AA   128

// Scratch buffers (device globals: allocation-free)
__device__ float g_K[BB * TV * AA];      // 2 MB
__device__ float g_Q[BB * TQ * AA];      // 0.5 MB
__device__ float g_attn[BB * TQ * TV];   // 4 MB

// ---------------------------------------------------------------------------
// fast math helpers
// ---------------------------------------------------------------------------
__device__ __forceinline__ float fast_ex2(float x) {
    float y;
    asm("ex2.approx.f32 %0, %1;" : "=f"(y) : "f"(x));
    return y;
}
__device__ __forceinline__ float ftanh(float x) {
    float y;
    asm("tanh.approx.f32 %0, %1;" : "=f"(y) : "f"(x));
    return y;
}

// ---------------------------------------------------------------------------
// Kernel A: fused K/Q projection, double-buffered.
// out[M,128] = X[M,512] @ W[512,128] + b
// BM=32, BN=128, BK=32, 256 threads, micro 4x4.
// grid = 128 + 32 = 160 CTAs (one wave).
// ---------------------------------------------------------------------------
#define PROJ_KBLKS ((BB * TV) / 32)   // 128
#define PROJ_NTILES (DD / 32)         // 16

__global__ void __launch_bounds__(256) proj_kernel(
    const float* __restrict__ inputs, const float* __restrict__ context,
    const float* __restrict__ Wk, const float* __restrict__ bk,
    const float* __restrict__ Wq, const float* __restrict__ bq)
{
    __shared__ float Xs[2][32][32];
    __shared__ float Ws[2][32][128];

    const int bx = blockIdx.x;
    const bool isK = (bx < PROJ_KBLKS);
    const float* X    = isK ? inputs : context;
    const float* W    = isK ? Wk : Wq;
    const float* bias = isK ? bk : bq;
    float* out        = isK ? g_K : g_Q;
    const int r0 = (isK ? bx : (bx - PROJ_KBLKS)) * 32;

    const int t  = threadIdx.x;
    const int tx = t & 31;        // col group: cols tx*4 .. tx*4+3
    const int ty = t >> 5;        // row group: rows ty*4 .. ty*4+3

    // per-thread fill coordinates
    const int xr = t >> 3, xc4 = (t & 7) * 4;      // Xs: 1 float4/thread
    const int wr = t >> 5, wc4 = (t & 31) * 4;     // Ws: 4 float4/thread (+8 rows)

    float acc[4][4] = {};

    // prologue: tile 0 -> buffer 0
    {
        *(float4*)&Xs[0][xr][xc4] = *(const float4*)&X[(size_t)(r0 + xr) * DD + xc4];
#pragma unroll
        for (int i = 0; i < 4; ++i)
            *(float4*)&Ws[0][wr + i * 8][wc4] =
                *(const float4*)&W[(size_t)(wr + i * 8) * AA + wc4];
    }
    __syncthreads();

    for (int kt = 0; kt < PROJ_NTILES; ++kt) {
        const int cur = kt & 1;
        float4 pX, pW0, pW1, pW2, pW3;
        const bool has_next = (kt + 1 < PROJ_NTILES);
        if (has_next) {          // prefetch next tile into registers (LDG now)
            const int k0 = (kt + 1) * 32;
            pX  = *(const float4*)&X[(size_t)(r0 + xr) * DD + k0 + xc4];
            pW0 = *(const float4*)&W[(size_t)(k0 + wr +  0) * AA + wc4];
            pW1 = *(const float4*)&W[(size_t)(k0 + wr +  8) * AA + wc4];
            pW2 = *(const float4*)&W[(size_t)(k0 + wr + 16) * AA + wc4];
            pW3 = *(const float4*)&W[(size_t)(k0 + wr + 24) * AA + wc4];
        }
#pragma unroll
        for (int k = 0; k < 32; ++k) {
            float4 wv = *(const float4*)&Ws[cur][k][tx * 4];
#pragma unroll
            for (int r = 0; r < 4; ++r) {
                float xv = Xs[cur][ty * 4 + r][k];
                acc[r][0] = fmaf(xv, wv.x, acc[r][0]);
                acc[r][1] = fmaf(xv, wv.y, acc[r][1]);
                acc[r][2] = fmaf(xv, wv.z, acc[r][2]);
                acc[r][3] = fmaf(xv, wv.w, acc[r][3]);
            }
        }
        if (has_next) {
            const int nxt = cur ^ 1;
            *(float4*)&Xs[nxt][xr][xc4] = pX;
            *(float4*)&Ws[nxt][wr +  0][wc4] = pW0;
            *(float4*)&Ws[nxt][wr +  8][wc4] = pW1;
            *(float4*)&Ws[nxt][wr + 16][wc4] = pW2;
            *(float4*)&Ws[nxt][wr + 24][wc4] = pW3;
            __syncthreads();
        }
    }

    float b0 = bias[tx * 4 + 0], b1 = bias[tx * 4 + 1];
    float b2 = bias[tx * 4 + 2], b3 = bias[tx * 4 + 3];
#pragma unroll
    for (int r = 0; r < 4; ++r) {
        float4 o;
        o.x = acc[r][0] + b0; o.y = acc[r][1] + b1;
        o.z = acc[r][2] + b2; o.w = acc[r][3] + b3;
        *(float4*)&out[(size_t)(r0 + ty * 4 + r) * AA + tx * 4] = o;
    }
}

// ---------------------------------------------------------------------------
// Kernel B: scores + softmax (unchanged).
// ---------------------------------------------------------------------------
#define KST_STRIDE 130
#define SMEMB_FLOATS (128 * KST_STRIDE + 4 * 128 + 128 + 4 * 1024)

__global__ void __launch_bounds__(256, 2) score_softmax_kernel(
    const int* __restrict__ mask, const float* __restrict__ attn_v)
{
    extern __shared__ float sm[];
    float* KsT = sm;                         // 128*130
    float* Qs  = KsT + 128 * KST_STRIDE;     // 512
    float* av  = Qs + 4 * 128;               // 128
    float* sc  = av + 128;                   // 4096

    const int t  = threadIdx.x;
    const int b  = blockIdx.y;
    const int q0 = blockIdx.x * 4;

    if (t < 128) {
        *(float4*)&Qs[t * 4] =
            *(const float4*)&g_Q[((size_t)(b * TQ + q0)) * AA + t * 4];
        av[t] = attn_v[t];
    }

    const int v0 = (t & 63) * 2;   // 2 adjacent v per thread
    const int q  = t >> 6;         // 0..3
    const int al = t & 127;        // a for the fill loop
    const int vh = t >> 7;         // 0/1

    for (int vt = 0; vt < TV / 128; ++vt) {
        const int vbase = vt * 128;
        __syncthreads();
        const float* Kp = g_K + ((size_t)b * TV + vbase) * AA;
#pragma unroll 8
        for (int i = 0; i < 64; ++i) {
            int vl = vh + 2 * i;
            KsT[al * KST_STRIDE + vl] = Kp[(size_t)vl * AA + al];
        }
        __syncthreads();

        float a0 = 0.f, a1 = 0.f;
#pragma unroll 4
        for (int a = 0; a < AA; ++a) {
            float2 kv = *(const float2*)&KsT[a * KST_STRIDE + v0];
            float qv = Qs[q * AA + a];
            float va = av[a];
            a0 = fmaf(va, ftanh(qv + kv.x), a0);
            a1 = fmaf(va, ftanh(qv + kv.y), a1);
        }
        *(float2*)&sc[q * TV + vbase + v0] = make_float2(a0, a1);
    }
    __syncthreads();

    const int w = t >> 5, lane = t & 31;
    if (w < 4) {
        float* row = sc + w * TV;
        const int* mrow = mask + (size_t)b * TV;
        float mx = -3.4e38f;
        for (int j = lane; j < TV; j += 32) {
            float s = row[j] + (1.0f - (float)mrow[j]) * (-1e9f);
            row[j] = s;
            mx = fmaxf(mx, s);
        }
#pragma unroll
        for (int o = 16; o; o >>= 1) mx = fmaxf(mx, __shfl_xor_sync(~0u, mx, o));
        float sum = 0.f;
        for (int j = lane; j < TV; j += 32) {
            float e = fast_ex2((row[j] - mx) * 1.4426950408889634f);
            row[j] = e;
            sum += e;
        }
#pragma unroll
        for (int o = 16; o; o >>= 1) sum += __shfl_xor_sync(~0u, sum, o);
        float inv = 1.0f / sum;
        float* arow = g_attn + ((size_t)(b * TQ + q0 + w)) * TV;
        for (int j = lane; j < TV; j += 32) arow[j] = row[j] * inv;
    }
}

// ---------------------------------------------------------------------------
// Kernel C: out[b,q,d] = sum_v attn[b,q,v] * inputs[b,v,d], double-buffered.
// BM=32(q), BN=64(d), BK=32(v), 256 threads, micro 2x4.
// grid: (8, 8, 4) = 256 CTAs -> 2 co-resident per SM.
// As stride 36: 144B rows keep float4 fills 16B-aligned; compute-read
// addresses differ by 72 mod 32 banks = 8 -> conflict-free 2-way broadcast.
// ---------------------------------------------------------------------------
__global__ void __launch_bounds__(256) av_kernel(
    const float* __restrict__ inp, float* __restrict__ out)
{
    __shared__ float As[2][32][36];
    __shared__ float Is[2][32][64];

    const int t  = threadIdx.x;
    const int tx = t & 15;        // col group: cols tx*4 .. tx*4+3 (of 64)
    const int ty = t >> 4;        // row group: rows ty*2, ty*2+1 (of 32)
    const int b  = blockIdx.z;
    const int q0 = blockIdx.y * 32;
    const int d0 = blockIdx.x * 64;

    // fill coordinates
    const int ar = t >> 3, ac4 = (t & 7) * 4;      // As: 32x32, 1 float4/thread
    const int ir = t >> 4, ic4 = (t & 15) * 4;     // Is: 2 float4/thread (+16 rows)

    float acc[2][4] = {};

    // prologue: tile 0
    {
        *(float4*)&As[0][ar][ac4] =
            *(const float4*)&g_attn[((size_t)(b * TQ + q0 + ar)) * TV + ac4];
        *(float4*)&Is[0][ir][ic4] =
            *(const float4*)&inp[((size_t)(b * TV + ir)) * DD + d0 + ic4];
        *(float4*)&Is[0][ir + 16][ic4] =
            *(const float4*)&inp[((size_t)(b * TV + ir + 16)) * DD + d0 + ic4];
    }
    __syncthreads();

    for (int vt = 0; vt < TV / 32; ++vt) {
        const int cur = vt & 1;
        const bool has_next = (vt + 1 < TV / 32);
        float4 pA, pI0, pI1;
        if (has_next) {
            const int v0 = (vt + 1) * 32;
            pA  = *(const float4*)&g_attn[((size_t)(b * TQ + q0 + ar)) * TV + v0 + ac4];
            pI0 = *(const float4*)&inp[((size_t)(b * TV + v0 + ir)) * DD + d0 + ic4];
            pI1 = *(const float4*)&inp[((size_t)(b * TV + v0 + ir + 16)) * DD + d0 + ic4];
        }
#pragma unroll
        for (int k = 0; k < 32; ++k) {
            float4 iv = *(const float4*)&Is[cur][k][tx * 4];
#pragma unroll
            for (int r = 0; r < 2; ++r) {
                float a = As[cur][ty * 2 + r][k];
                acc[r][0] = fmaf(a, iv.x, acc[r][0]);
                acc[r][1] = fmaf(a, iv.y, acc[r][1]);
                acc[r][2] = fmaf(a, iv.z, acc[r][2]);
                acc[r][3] = fmaf(a, iv.w, acc[r][3]);
            }
        }
        if (has_next) {
            const int nxt = cur ^ 1;
            *(float4*)&As[nxt][ar][ac4] = pA;
            *(float4*)&Is[nxt][ir][ic4] = pI0;
            *(float4*)&Is[nxt][ir + 16][ic4] = pI1;
            __syncthreads();
        }
    }

#pragma unroll
    for (int r = 0; r < 2; ++r) {
        float4 o;
        o.x = acc[r][0]; o.y = acc[r][1]; o.z = acc[r][2]; o.w = acc[r][3];
        *(float4*)&out[((size_t)(b * TQ + q0 + ty * 2 + r)) * DD + d0 + tx * 4] = o;
    }
}

// ---------------------------------------------------------------------------
extern "C" void kernel_launch(void* const* d_in, const int* in_sizes, int n_in,
                              void* d_out, int out_size)
{
    (void)in_sizes; (void)n_in; (void)out_size;
    const float* inputs  = (const float*)d_in[0];   // [B,Tv,D]
    const float* context = (const float*)d_in[1];   // [B,Tq,D]
    const int*   mask    = (const int*)  d_in[2];   // [B,Tv]
    const float* Wk      = (const float*)d_in[3];   // [D,A]
    const float* bk      = (const float*)d_in[4];   // [A]
    const float* Wq      = (const float*)d_in[5];   // [D,A]
    const float* bq      = (const float*)d_in[6];   // [A]
    const float* attn_v  = (const float*)d_in[7];   // [A]
    float* out = (float*)d_out;                     // [B,Tq,D]

    static const size_t smemB = SMEMB_FLOATS * sizeof(float);
    cudaFuncSetAttribute(score_softmax_kernel,
                         cudaFuncAttributeMaxDynamicSharedMemorySize, (int)smemB);

    // K = inputs @ Wk + bk ; Q = context @ Wq + bq  (fused, 160 CTAs)
    proj_kernel<<<PROJ_KBLKS + (BB * TQ) / 32, 256>>>(
        inputs, context, Wk, bk, Wq, bq);
    // scores + softmax -> g_attn
    {
        dim3 grid(TQ / 4, BB);
        score_softmax_kernel<<<grid, 256, smemB>>>(mask, attn_v);
    }
    // out = attn @ inputs
    {
        dim3 grid(DD / 64, TQ / 32, BB);
        av_kernel<<<grid, 256>>>(inputs, out);
    }
}